// round 6
// baseline (speedup 1.0000x reference)
#include <cuda_runtime.h>
#include <math.h>
#include <stdint.h>

#define DZ 64
#define DC 32
#define TILE 128
#define THREADS 128

// Packed f32x2 ops (Blackwell FFMA2 path)
#define FMA_F32X2(acc, a, b) \
    asm("fma.rn.f32x2 %0, %1, %2, %0;" : "+l"(acc) : "l"(a), "l"(b))
#define ADD_F32X2(d, a, b) \
    asm("add.rn.f32x2 %0, %1, %2;" : "=l"(d) : "l"(a), "l"(b))
#define REDUX_MAX_U32(dst, src) \
    asm("redux.sync.max.u32 %0, %1, 0xffffffff;" : "=r"(dst) : "r"(src))

// Monotone float->uint encoding, low 5 bits replaced by (31-lane) for
// first-index-preferring argmax via a single redux.max.
__device__ __forceinline__ unsigned enc_logit(float l, int lane) {
    unsigned u = __float_as_uint(l);
    u = (u & 0x80000000u) ? ~u : (u | 0x80000000u);
    return (u & 0xFFFFFFE0u) | (unsigned)(31 - lane);
}
// Approximate decode (channel bits cleared); error <= 32 ulp (~1e-6 here),
// fully covered by the exact-path screen.
__device__ __forceinline__ float dec_logit(unsigned e) {
    e &= 0xFFFFFFE0u;
    return (e & 0x80000000u) ? __uint_as_float(e ^ 0x80000000u)
                             : __uint_as_float(~e);
}

// Decide one row's channel. l = this lane's (=channel's) fp32 logit.
// Fast: 2 redux. Rare (top-2 gap < 4e-6): exact reference emulation
// (proven in R3): double-accumulated logits -> fp32 -> exp -> sequential
// norm -> IEEE divide -> first-index argmax over probs.
__device__ __forceinline__ int decide_row(float l, const float* __restrict__ zrow,
                                          const float* __restrict__ beta, int lane)
{
    const unsigned e1 = enc_logit(l, lane);
    unsigned m1;
    REDUX_MAX_U32(m1, e1);
    int idx = 31 - (int)(m1 & 31u);

    const unsigned e2 = (lane == idx) ? 0u : e1;
    unsigned m2;
    REDUX_MAX_U32(m2, e2);

    if (dec_logit(m1) - dec_logit(m2) < 4e-6f) {
        int bi = 0;
        if (lane == 0) {
            float e[DC];
#pragma unroll 1
            for (int c = 0; c < DC - 1; c++) {
                double sd = 0.0;
#pragma unroll 1
                for (int d = 0; d < DZ; d++)
                    sd += (double)zrow[d] * (double)beta[c * DZ + d];
                float lf = (float)sd;
                e[c] = (float)exp((double)lf);
            }
            e[DC - 1] = 1.0f;
            float se = e[0];
#pragma unroll 1
            for (int c = 1; c < DC - 1; c++) se += e[c];
            const float norm = 1.0f + se;
            float pb = -1.0f;
#pragma unroll 1
            for (int c = 0; c < DC; c++) {
                float p = __fdiv_rn(e[c], norm);
                if (p > pb) { pb = p; bi = c; }   // strict > = first index
            }
        }
        idx = __shfl_sync(0xffffffffu, bi, 0);
    }
    return idx;
}

__global__ __launch_bounds__(THREADS, 4)
void dec_cat_kernel(const float* __restrict__ Z,
                    const float* __restrict__ beta,
                    float* __restrict__ out,
                    int T)
{
    __shared__ float zs[TILE][DZ];   // 32 KB; rows 256B -> 16B-aligned u64x2 reads

    const int tid  = threadIdx.x;
    const int lane = tid & 31;
    const int w    = tid >> 5;
    const int rowBase = blockIdx.x * TILE;
    const int rowsHere = min(TILE, T - rowBase);

    // ---- beta in registers: lane c holds channel c's 64 coeffs as 32 packed
    //      d-pairs. Channel 31 (implicit) = zeros -> logit exactly +0. ----
    unsigned long long br[DZ / 2];
    if (lane < DC - 1) {
        const ulonglong2* bp = reinterpret_cast<const ulonglong2*>(beta + lane * DZ);
#pragma unroll
        for (int q = 0; q < 16; q++) {
            ulonglong2 v = bp[q];
            br[2 * q]     = v.x;
            br[2 * q + 1] = v.y;
        }
    } else {
#pragma unroll
        for (int q = 0; q < DZ / 2; q++) br[q] = 0ull;
    }

    // ---- stage Z tile: coalesced float4 loads -> smem ----
    {
        const float4* Z4 = reinterpret_cast<const float4*>(Z + (size_t)rowBase * DZ);
        const int n4 = rowsHere * (DZ / 4);
        float4* zs4 = reinterpret_cast<float4*>(&zs[0][0]);
        for (int i = tid; i < n4; i += THREADS) zs4[i] = Z4[i];
    }
    __syncthreads();

    const int rw0 = w * 32;      // warp's 32 rows

#pragma unroll 1
    for (int i = 0; i < 32; i += 2) {
        const int r0 = rw0 + i;
        if (r0 >= rowsHere) break;
        const bool two = (r0 + 1 < rowsHere);
        const int r1 = two ? r0 + 1 : r0;

        const ulonglong2* zp0 = reinterpret_cast<const ulonglong2*>(&zs[r0][0]);
        const ulonglong2* zp1 = reinterpret_cast<const ulonglong2*>(&zs[r1][0]);

        // two independent 4-chain accumulator sets (row0: a*, row1: b*)
        unsigned long long a0 = 0ull, a1 = 0ull, a2 = 0ull, a3 = 0ull;
        unsigned long long b0 = 0ull, b1 = 0ull, b2 = 0ull, b3 = 0ull;
#pragma unroll
        for (int q = 0; q < 8; q++) {
            ulonglong2 x0 = zp0[2 * q];
            ulonglong2 y0 = zp0[2 * q + 1];
            ulonglong2 x1 = zp1[2 * q];
            ulonglong2 y1 = zp1[2 * q + 1];
            FMA_F32X2(a0, x0.x, br[4 * q + 0]);
            FMA_F32X2(b0, x1.x, br[4 * q + 0]);
            FMA_F32X2(a1, x0.y, br[4 * q + 1]);
            FMA_F32X2(b1, x1.y, br[4 * q + 1]);
            FMA_F32X2(a2, y0.x, br[4 * q + 2]);
            FMA_F32X2(b2, y1.x, br[4 * q + 2]);
            FMA_F32X2(a3, y0.y, br[4 * q + 3]);
            FMA_F32X2(b3, y1.y, br[4 * q + 3]);
        }
        // same reduction order as the proven R3 kernel
        ADD_F32X2(a0, a0, a1);  ADD_F32X2(a2, a2, a3);  ADD_F32X2(a0, a0, a2);
        ADD_F32X2(b0, b0, b1);  ADD_F32X2(b2, b2, b3);  ADD_F32X2(b0, b0, b2);

        float lo0, hi0, lo1, hi1;
        asm("mov.b64 {%0, %1}, %2;" : "=f"(lo0), "=f"(hi0) : "l"(a0));
        asm("mov.b64 {%0, %1}, %2;" : "=f"(lo1), "=f"(hi1) : "l"(b0));
        const float l0 = lo0 + hi0;      // lane c's logit, row r0 (lane31 -> +0)
        const float l1 = lo1 + hi1;      // row r1

        const int idx0 = decide_row(l0, &zs[r0][0], beta, lane);
        const int idx1 = two ? decide_row(l1, &zs[r1][0], beta, lane) : idx0;

        // ---- one-hot: lanes 0-15 cover row r0, lanes 16-31 row r1;
        //      one STG.64 per lane writes 2 channels (coalesced 256B) ----
        const int rr = (lane >= 16) ? r1 : r0;
        const int ii = (lane >= 16) ? idx1 : idx0;
        const int ch = (lane & 15) * 2;
        if (two || lane < 16) {
            float2 v;
            v.x = (ch     == ii) ? 1.0f : 0.0f;
            v.y = (ch + 1 == ii) ? 1.0f : 0.0f;
            *reinterpret_cast<float2*>(out + (size_t)(rowBase + rr) * DC + ch) = v;
        }
    }
}

extern "C" void kernel_launch(void* const* d_in, const int* in_sizes, int n_in,
                              void* d_out, int out_size)
{
    const float* Z    = (const float*)d_in[0];
    const float* beta = (const float*)d_in[1];
    float* out        = (float*)d_out;

    const int T = in_sizes[0] / DZ;
    const int grid = (T + TILE - 1) / TILE;

    dec_cat_kernel<<<grid, THREADS>>>(Z, beta, out, T);
}

// round 7
// speedup vs baseline: 1.0164x; 1.0164x over previous
#include <cuda_runtime.h>
#include <math.h>
#include <stdint.h>

#define DZ 64
#define DC 32
#define TILE 128
#define THREADS 128
#define ZS_STRIDE 68          // floats/row: conflict-free frag loads
#define BS_STRIDE 65          // padded beta row: conflict-free bs[c*65+d] reads
#define TH_FAST 2.5e-4f       // tf32 -> exact-fp32 re-decide trigger
#define TH_MED  4e-6f         // fp32 -> exact-double re-decide trigger (R6-proven)
#define TH_CHK  1.5e-3f       // canary tolerance (layout bug shows at ~5e-3+)

__device__ __forceinline__ uint32_t to_tf32(float f) {
    uint32_t r;
    asm("cvt.rna.tf32.f32 %0, %1;" : "=r"(r) : "f"(f));
    return r;
}

#define MMA_TF32(C, a0, a1, a2, a3, b0, b1)                                   \
    asm("mma.sync.aligned.m16n8k8.row.col.f32.tf32.tf32.f32 "                 \
        "{%0,%1,%2,%3}, {%4,%5,%6,%7}, {%8,%9}, {%0,%1,%2,%3};"               \
        : "+f"(C[0]), "+f"(C[1]), "+f"(C[2]), "+f"(C[3])                      \
        : "r"(a0), "r"(a1), "r"(a2), "r"(a3), "r"(b0), "r"(b1))

__global__ __launch_bounds__(THREADS, 3)
void dec_cat_kernel(const float* __restrict__ Z,
                    const float* __restrict__ beta,
                    float* __restrict__ out,
                    int T)
{
    __shared__ float zs[TILE * ZS_STRIDE];       // exact fp32 z tile (padded)
    __shared__ float bs[(DC - 1) * BS_STRIDE];   // exact fp32 beta, padded rows

    const int tid  = threadIdx.x;
    const int lane = tid & 31;
    const int w    = tid >> 5;
    const int a    = lane & 3;    // threadID in group
    const int g    = lane >> 2;   // groupID (quad)
    const int rowBase = blockIdx.x * TILE;

    // ---- exact beta copy (padded) for canary/medium/exact paths ----
    for (int i = tid; i < (DC - 1) * DZ; i += THREADS)
        bs[(i >> 6) * BS_STRIDE + (i & 63)] = beta[i];

    // ---- B fragments (tf32) in registers: b0=(k=a, n=g), b1=(k=a+4, n=g) ----
    uint32_t bf[8][4][2];
#pragma unroll
    for (int kt = 0; kt < 8; kt++)
#pragma unroll
        for (int nt = 0; nt < 4; nt++) {
            int n  = nt * 8 + g;
            int k0 = kt * 8 + a;
            float f0 = (n < DC - 1) ? beta[n * DZ + k0]     : 0.0f;
            float f1 = (n < DC - 1) ? beta[n * DZ + k0 + 4] : 0.0f;
            bf[kt][nt][0] = to_tf32(f0);
            bf[kt][nt][1] = to_tf32(f1);
        }

    // ---- stage Z tile: coalesced float4 loads -> padded smem (exact fp32) ----
    {
        const int rowsHere = min(TILE, T - rowBase);
        const float4* Z4 = reinterpret_cast<const float4*>(Z + (size_t)rowBase * DZ);
        const int n4 = rowsHere * (DZ / 4);
        for (int i = tid; i < n4; i += THREADS) {
            float4 v = Z4[i];
            int r = i >> 4, c4 = i & 15;
            *reinterpret_cast<float4*>(&zs[r * ZS_STRIDE + c4 * 4]) = v;
        }
    }
    __syncthreads();

    const int rw0 = w * 32;      // warp's 32-row sub-tile

    // ---- mainloop: 32x32x64 warp GEMM via tf32 mma ----
    float C[2][4][4];
#pragma unroll
    for (int mt = 0; mt < 2; mt++)
#pragma unroll
        for (int nt = 0; nt < 4; nt++)
#pragma unroll
            for (int j = 0; j < 4; j++) C[mt][nt][j] = 0.0f;

#pragma unroll
    for (int kt = 0; kt < 8; kt++) {
        const int k0 = kt * 8 + a;
#pragma unroll
        for (int mt = 0; mt < 2; mt++) {
            const int r0 = rw0 + mt * 16 + g;
            uint32_t a0 = to_tf32(zs[r0 * ZS_STRIDE + k0]);
            uint32_t a1 = to_tf32(zs[(r0 + 8) * ZS_STRIDE + k0]);
            uint32_t a2 = to_tf32(zs[r0 * ZS_STRIDE + k0 + 4]);
            uint32_t a3 = to_tf32(zs[(r0 + 8) * ZS_STRIDE + k0 + 4]);
#pragma unroll
            for (int nt = 0; nt < 4; nt++)
                MMA_TF32(C[mt][nt], a0, a1, a2, a3, bf[kt][nt][0], bf[kt][nt][1]);
        }
    }

    // ---- CANARY: validate fragment/C interpretation on rows rw0, rw0+8 ----
    int bad = 0;
#pragma unroll
    for (int h = 0; h < 2; h++) {
        const float* zr = &zs[(rw0 + h * 8) * ZS_STRIDE];
        float l = 0.0f;
        if (lane < DC - 1) {
            const float* br = &bs[lane * BS_STRIDE];
            float s0 = 0.0f, s1 = 0.0f;
#pragma unroll
            for (int q = 0; q < 16; q++) {
                float4 zq = *reinterpret_cast<const float4*>(&zr[4 * q]);
                s0 = fmaf(zq.x, br[4 * q + 0], s0);
                s1 = fmaf(zq.y, br[4 * q + 1], s1);
                s0 = fmaf(zq.z, br[4 * q + 2], s0);
                s1 = fmaf(zq.w, br[4 * q + 3], s1);
            }
            l = s0 + s1;
        }
#pragma unroll
        for (int nt = 0; nt < 4; nt++)
#pragma unroll
            for (int j = 0; j < 2; j++) {
                int ch = nt * 8 + 2 * a + j;
                float le = __shfl_sync(0xffffffffu, l, ch);
                if (g == 0 && fabsf(C[0][nt][h * 2 + j] - le) > TH_CHK) bad = 1;
            }
    }
    const bool fallback = (__ballot_sync(0xffffffffu, bad) != 0u);

    // ---- epilogue: per row-slot argmax + ambiguity flagging ----
    int idxs[4];
    unsigned flagm[4];
    if (!fallback) {
#pragma unroll
        for (int s = 0; s < 4; s++) {
            const int mt = s >> 1, h = s & 1;
            float best = C[mt][0][h * 2];
            int   bch  = 2 * a;
#pragma unroll
            for (int nt = 0; nt < 4; nt++)
#pragma unroll
                for (int j = 0; j < 2; j++) {
                    float v = C[mt][nt][h * 2 + j];
                    int  ch = nt * 8 + 2 * a + j;
                    if (v > best) { best = v; bch = ch; }
                }
#pragma unroll
            for (int off = 1; off <= 2; off <<= 1) {
                float ov = __shfl_xor_sync(0xffffffffu, best, off);
                int   oc = __shfl_xor_sync(0xffffffffu, bch,  off);
                if (ov > best) { best = ov; bch = oc; }
            }
            int cnt = 0;
            const float th = best - TH_FAST;
#pragma unroll
            for (int nt = 0; nt < 4; nt++)
#pragma unroll
                for (int j = 0; j < 2; j++)
                    cnt += (C[mt][nt][h * 2 + j] >= th);
            cnt += __shfl_xor_sync(0xffffffffu, cnt, 1);
            cnt += __shfl_xor_sync(0xffffffffu, cnt, 2);

            idxs[s]  = bch;
            flagm[s] = __ballot_sync(0xffffffffu, cnt > 1);
        }
    } else {
#pragma unroll
        for (int s = 0; s < 4; s++) { idxs[s] = 0; flagm[s] = 0xFFFFFFFFu; }
    }

    // ---- exact path for flagged rows (all rows, if fallback engaged) ----
#pragma unroll 1
    for (int s = 0; s < 4; s++) {
        unsigned m = flagm[s] & 0x11111111u;   // one representative bit per quad
#pragma unroll 1
        while (m) {
            const int b = __ffs(m) - 1;
            m &= m - 1;
            const int q    = b >> 2;
            const int rloc = (s >> 1) * 16 + q + (s & 1) * 8;
            const int gr   = rowBase + rw0 + rloc;
            if (gr >= T) continue;

            // FIX (R5 bug): read THIS WARP's row: rw0 + rloc
            const float* zrow = &zs[(rw0 + rloc) * ZS_STRIDE];

            // lane = channel; exact fp32 z + exact fp32 beta (conflict-free)
            float l = 0.0f;
            if (lane < DC - 1) {
                const float* br = &bs[lane * BS_STRIDE];
                float s0 = 0.0f, s1 = 0.0f;
#pragma unroll
                for (int q2 = 0; q2 < 16; q2++) {
                    float4 zq = *reinterpret_cast<const float4*>(&zrow[4 * q2]);
                    s0 = fmaf(zq.x, br[4 * q2 + 0], s0);
                    s1 = fmaf(zq.y, br[4 * q2 + 1], s1);
                    s0 = fmaf(zq.z, br[4 * q2 + 2], s0);
                    s1 = fmaf(zq.w, br[4 * q2 + 3], s1);
                }
                l = s0 + s1;
            }
            unsigned u = __float_as_uint(l);
            u = (u & 0x80000000u) ? ~u : (u | 0x80000000u);
            unsigned umax;
            asm("redux.sync.max.u32 %0, %1, 0xffffffff;" : "=r"(umax) : "r"(u));
            const float mx = (umax & 0x80000000u)
                               ? __uint_as_float(umax ^ 0x80000000u)
                               : __uint_as_float(~umax);
            const unsigned nearMask = __ballot_sync(0xffffffffu, l >= mx - TH_MED);
            int idx;
            if (__popc(nearMask) == 1) {
                idx = __ffs(nearMask) - 1;
            } else {
                // exact reference emulation: double accumulate -> fp32 -> exp
                // -> sequential norm -> IEEE divide -> first-index argmax
                int bi = 0;
                if (lane == 0) {
                    float e[DC];
#pragma unroll 1
                    for (int c = 0; c < DC - 1; c++) {
                        double sd = 0.0;
#pragma unroll 1
                        for (int d = 0; d < DZ; d++)
                            sd += (double)zrow[d] * (double)bs[c * BS_STRIDE + d];
                        float lf = (float)sd;
                        e[c] = (float)exp((double)lf);
                    }
                    e[DC - 1] = 1.0f;
                    float se = e[0];
#pragma unroll 1
                    for (int c = 1; c < DC - 1; c++) se += e[c];
                    const float norm = 1.0f + se;
                    float pb = -1.0f;
#pragma unroll 1
                    for (int c = 0; c < DC; c++) {
                        float p = __fdiv_rn(e[c], norm);
                        if (p > pb) { pb = p; bi = c; }   // strict > = first index
                    }
                }
                idx = __shfl_sync(0xffffffffu, bi, 0);
            }
            if (g == q) idxs[s] = idx;   // owning quad adopts the decision
        }
    }

    // ---- one-hot stores: 4 x STG.64 per slot (quad-parallel) ----
#pragma unroll
    for (int s = 0; s < 4; s++) {
        const int rloc = (s >> 1) * 16 + g + (s & 1) * 8;
        const int gr   = rowBase + rw0 + rloc;
        if (gr < T) {
            float* o = out + (size_t)gr * DC + 2 * a;
#pragma unroll
            for (int nt = 0; nt < 4; nt++) {
                const int ch0 = nt * 8 + 2 * a;
                float2 v;
                v.x = (ch0     == idxs[s]) ? 1.0f : 0.0f;
                v.y = (ch0 + 1 == idxs[s]) ? 1.0f : 0.0f;
                *reinterpret_cast<float2*>(o + nt * 8) = v;
            }
        }
    }
}

extern "C" void kernel_launch(void* const* d_in, const int* in_sizes, int n_in,
                              void* d_out, int out_size)
{
    const float* Z    = (const float*)d_in[0];
    const float* beta = (const float*)d_in[1];
    float* out        = (float*)d_out;

    const int T = in_sizes[0] / DZ;
    const int grid = (T + TILE - 1) / TILE;

    dec_cat_kernel<<<grid, THREADS>>>(Z, beta, out, T);
}

// round 8
// speedup vs baseline: 1.1330x; 1.1147x over previous
#include <cuda_runtime.h>
#include <math.h>
#include <stdint.h>

#define DZ 64
#define DC 32
#define TILE 128
#define THREADS 128
#define ZS_STRIDE 68          // floats/row: conflict-free frag loads
#define BS_STRIDE 65          // padded beta row: conflict-free bs[c*65+d] reads
#define TH_FAST 2.5e-4f       // tf32 -> exact-fp32 re-decide trigger (proven R7)
#define TH_MED  4e-6f         // fp32 -> exact-double re-decide trigger (proven R6/R7)

__device__ __forceinline__ uint32_t to_tf32(float f) {
    uint32_t r;
    asm("cvt.rna.tf32.f32 %0, %1;" : "=r"(r) : "f"(f));
    return r;
}

#define MMA_TF32(C, a0, a1, a2, a3, b0, b1)                                   \
    asm("mma.sync.aligned.m16n8k8.row.col.f32.tf32.tf32.f32 "                 \
        "{%0,%1,%2,%3}, {%4,%5,%6,%7}, {%8,%9}, {%0,%1,%2,%3};"               \
        : "+f"(C[0]), "+f"(C[1]), "+f"(C[2]), "+f"(C[3])                      \
        : "r"(a0), "r"(a1), "r"(a2), "r"(a3), "r"(b0), "r"(b1))

// Cold path: exact reference emulation (proven R3/R6/R7). Kept out of the hot
// path's register allocation. Called by all 32 lanes; lane 0 computes.
//   double accumulate -> fp32 -> exp -> sequential norm -> IEEE divide
//   -> first-index argmax over probs.
__device__ __noinline__ int decide_exact(const float* __restrict__ zrow,
                                         const float* __restrict__ bs,
                                         int lane)
{
    int bi = 0;
    if (lane == 0) {
        float e[DC];
#pragma unroll 1
        for (int c = 0; c < DC - 1; c++) {
            double sd = 0.0;
#pragma unroll 1
            for (int d = 0; d < DZ; d++)
                sd += (double)zrow[d] * (double)bs[c * BS_STRIDE + d];
            float lf = (float)sd;
            e[c] = (float)exp((double)lf);
        }
        e[DC - 1] = 1.0f;
        float se = e[0];
#pragma unroll 1
        for (int c = 1; c < DC - 1; c++) se += e[c];
        const float norm = 1.0f + se;
        float pb = -1.0f;
#pragma unroll 1
        for (int c = 0; c < DC; c++) {
            float p = __fdiv_rn(e[c], norm);
            if (p > pb) { pb = p; bi = c; }   // strict > = first index
        }
    }
    return __shfl_sync(0xffffffffu, bi, 0);
}

__global__ __launch_bounds__(THREADS, 4)
void dec_cat_kernel(const float* __restrict__ Z,
                    const float* __restrict__ beta,
                    float* __restrict__ out,
                    int T)
{
    __shared__ float zs[TILE * ZS_STRIDE];       // exact fp32 z tile (padded)
    __shared__ float bs[(DC - 1) * BS_STRIDE];   // exact fp32 beta, padded rows

    const int tid  = threadIdx.x;
    const int lane = tid & 31;
    const int w    = tid >> 5;
    const int a    = lane & 3;    // threadID in group
    const int g    = lane >> 2;   // groupID (quad)
    const int rowBase = blockIdx.x * TILE;

    // ---- exact beta copy (padded) for medium/exact paths ----
    for (int i = tid; i < (DC - 1) * DZ; i += THREADS)
        bs[(i >> 6) * BS_STRIDE + (i & 63)] = beta[i];

    // ---- B fragments (tf32) in registers: b0=(k=a, n=g), b1=(k=a+4, n=g) ----
    uint32_t bf[8][4][2];
#pragma unroll
    for (int kt = 0; kt < 8; kt++)
#pragma unroll
        for (int nt = 0; nt < 4; nt++) {
            int n  = nt * 8 + g;
            int k0 = kt * 8 + a;
            float f0 = (n < DC - 1) ? beta[n * DZ + k0]     : 0.0f;
            float f1 = (n < DC - 1) ? beta[n * DZ + k0 + 4] : 0.0f;
            bf[kt][nt][0] = to_tf32(f0);
            bf[kt][nt][1] = to_tf32(f1);
        }

    // ---- stage Z tile: coalesced float4 loads -> padded smem (exact fp32) ----
    {
        const int rowsHere = min(TILE, T - rowBase);
        const float4* Z4 = reinterpret_cast<const float4*>(Z + (size_t)rowBase * DZ);
        const int n4 = rowsHere * (DZ / 4);
        for (int i = tid; i < n4; i += THREADS) {
            float4 v = Z4[i];
            int r = i >> 4, c4 = i & 15;
            *reinterpret_cast<float4*>(&zs[r * ZS_STRIDE + c4 * 4]) = v;
        }
    }
    __syncthreads();

    const int rw0 = w * 32;      // warp's 32-row sub-tile

    // ---- mainloop: 32x32x64 warp GEMM via tf32 mma ----
    float C[2][4][4];
#pragma unroll
    for (int mt = 0; mt < 2; mt++)
#pragma unroll
        for (int nt = 0; nt < 4; nt++)
#pragma unroll
            for (int j = 0; j < 4; j++) C[mt][nt][j] = 0.0f;

#pragma unroll
    for (int kt = 0; kt < 8; kt++) {
        const int k0 = kt * 8 + a;
#pragma unroll
        for (int mt = 0; mt < 2; mt++) {
            const int r0 = rw0 + mt * 16 + g;
            uint32_t a0 = to_tf32(zs[r0 * ZS_STRIDE + k0]);
            uint32_t a1 = to_tf32(zs[(r0 + 8) * ZS_STRIDE + k0]);
            uint32_t a2 = to_tf32(zs[r0 * ZS_STRIDE + k0 + 4]);
            uint32_t a3 = to_tf32(zs[(r0 + 8) * ZS_STRIDE + k0 + 4]);
#pragma unroll
            for (int nt = 0; nt < 4; nt++)
                MMA_TF32(C[mt][nt], a0, a1, a2, a3, bf[kt][nt][0], bf[kt][nt][1]);
        }
    }

    // ---- epilogue: per row-slot argmax + ambiguity flagging (proven R7) ----
    int idxs[4];
    unsigned flagm[4];
#pragma unroll
    for (int s = 0; s < 4; s++) {
        const int mt = s >> 1, h = s & 1;
        float best = C[mt][0][h * 2];
        int   bch  = 2 * a;
#pragma unroll
        for (int nt = 0; nt < 4; nt++)
#pragma unroll
            for (int j = 0; j < 2; j++) {
                float v = C[mt][nt][h * 2 + j];
                int  ch = nt * 8 + 2 * a + j;
                if (v > best) { best = v; bch = ch; }
            }
#pragma unroll
        for (int off = 1; off <= 2; off <<= 1) {
            float ov = __shfl_xor_sync(0xffffffffu, best, off);
            int   oc = __shfl_xor_sync(0xffffffffu, bch,  off);
            if (ov > best) { best = ov; bch = oc; }
        }
        int cnt = 0;
        const float th = best - TH_FAST;
#pragma unroll
        for (int nt = 0; nt < 4; nt++)
#pragma unroll
            for (int j = 0; j < 2; j++)
                cnt += (C[mt][nt][h * 2 + j] >= th);
        cnt += __shfl_xor_sync(0xffffffffu, cnt, 1);
        cnt += __shfl_xor_sync(0xffffffffu, cnt, 2);

        idxs[s]  = bch;
        flagm[s] = __ballot_sync(0xffffffffu, cnt > 1);
    }

    // ---- re-decide flagged rows (medium exact-fp32, then exact-double) ----
#pragma unroll 1
    for (int s = 0; s < 4; s++) {
        unsigned m = flagm[s] & 0x11111111u;   // one representative bit per quad
#pragma unroll 1
        while (m) {
            const int b = __ffs(m) - 1;
            m &= m - 1;
            const int q    = b >> 2;
            const int rloc = (s >> 1) * 16 + q + (s & 1) * 8;
            const int gr   = rowBase + rw0 + rloc;
            if (gr >= T) continue;

            const float* zrow = &zs[(rw0 + rloc) * ZS_STRIDE];   // THIS warp's row

            // lane = channel; exact fp32 z + exact fp32 beta (conflict-free)
            float l = 0.0f;
            if (lane < DC - 1) {
                const float* br = &bs[lane * BS_STRIDE];
                float s0 = 0.0f, s1 = 0.0f;
#pragma unroll
                for (int q2 = 0; q2 < 16; q2++) {
                    float4 zq = *reinterpret_cast<const float4*>(&zrow[4 * q2]);
                    s0 = fmaf(zq.x, br[4 * q2 + 0], s0);
                    s1 = fmaf(zq.y, br[4 * q2 + 1], s1);
                    s0 = fmaf(zq.z, br[4 * q2 + 2], s0);
                    s1 = fmaf(zq.w, br[4 * q2 + 3], s1);
                }
                l = s0 + s1;
            }
            unsigned u = __float_as_uint(l);
            u = (u & 0x80000000u) ? ~u : (u | 0x80000000u);
            unsigned umax;
            asm("redux.sync.max.u32 %0, %1, 0xffffffff;" : "=r"(umax) : "r"(u));
            const float mx = (umax & 0x80000000u)
                               ? __uint_as_float(umax ^ 0x80000000u)
                               : __uint_as_float(~umax);
            const unsigned nearMask = __ballot_sync(0xffffffffu, l >= mx - TH_MED);
            int idx;
            if (__popc(nearMask) == 1) {
                idx = __ffs(nearMask) - 1;
            } else {
                idx = decide_exact(zrow, bs, lane);
            }
            if (g == q) idxs[s] = idx;   // owning quad adopts the decision
        }
    }

    // ---- one-hot stores: 4 x STG.64 per slot (quad-parallel) ----
#pragma unroll
    for (int s = 0; s < 4; s++) {
        const int rloc = (s >> 1) * 16 + g + (s & 1) * 8;
        const int gr   = rowBase + rw0 + rloc;
        if (gr < T) {
            float* o = out + (size_t)gr * DC + 2 * a;
#pragma unroll
            for (int nt = 0; nt < 4; nt++) {
                const int ch0 = nt * 8 + 2 * a;
                float2 v;
                v.x = (ch0     == idxs[s]) ? 1.0f : 0.0f;
                v.y = (ch0 + 1 == idxs[s]) ? 1.0f : 0.0f;
                *reinterpret_cast<float2*>(o + nt * 8) = v;
            }
        }
    }
}

extern "C" void kernel_launch(void* const* d_in, const int* in_sizes, int n_in,
                              void* d_out, int out_size)
{
    const float* Z    = (const float*)d_in[0];
    const float* beta = (const float*)d_in[1];
    float* out        = (float*)d_out;

    const int T = in_sizes[0] / DZ;
    const int grid = (T + TILE - 1) / TILE;

    dec_cat_kernel<<<grid, THREADS>>>(Z, beta, out, T);
}